// round 8
// baseline (speedup 1.0000x reference)
#include <cuda_runtime.h>

// Problem constants
constexpr int kS = 2048;   // seq len
constexpr int kB = 64;     // batch
constexpr int kE = 512;    // embed
constexpr int kH = 256;    // hidden
constexpr int kG = 1024;   // 4*H

// Scratch for input projections: [2 dirs][S][B][4H] fp32 = 1.07 GB
__device__ float g_gx[2u * 2048u * 64u * 1024u];

// ---------------------------------------------------------------------------
// Helpers
// ---------------------------------------------------------------------------
__device__ __forceinline__ unsigned f2tf(float x) {
    unsigned r;
    asm("cvt.rna.tf32.f32 %0, %1;" : "=r"(r) : "f"(x));
    return r;
}

__device__ __forceinline__ void mma_tf32(float* c, const unsigned* a, const unsigned* b) {
    asm volatile(
        "mma.sync.aligned.m16n8k8.row.col.f32.tf32.tf32.f32 "
        "{%0,%1,%2,%3},{%4,%5,%6,%7},{%8,%9},{%0,%1,%2,%3};"
        : "+f"(c[0]), "+f"(c[1]), "+f"(c[2]), "+f"(c[3])
        : "r"(a[0]), "r"(a[1]), "r"(a[2]), "r"(a[3]), "r"(b[0]), "r"(b[1]));
}

__device__ __forceinline__ float sigf(float x) { return 1.f / (1.f + __expf(-x)); }
__device__ __forceinline__ float tanhf_(float x) { return 1.f - 2.f / (__expf(2.f * x) + 1.f); }

// ---------------------------------------------------------------------------
// Kernel 1: input projection GEMM (tf32 mma.sync), per direction (unchanged)
// ---------------------------------------------------------------------------
__global__ void __launch_bounds__(128) gemm_in(
    const float* __restrict__ X,
    const float* __restrict__ Wf, const float* __restrict__ bif, const float* __restrict__ bhf,
    const float* __restrict__ Wb, const float* __restrict__ bib, const float* __restrict__ bhb)
{
    __shared__ unsigned As[64 * 20];
    __shared__ unsigned Bs[64 * 20];

    const int ntile = blockIdx.x;       // 0..15
    const int s     = blockIdx.y;       // 0..2047
    const int d     = blockIdx.z;       // 0..1
    const float* W  = d == 0 ? Wf : Wb;
    const float* bi = d == 0 ? bif : bib;
    const float* bh = d == 0 ? bhf : bhb;
    const int n0 = ntile * 64;

    const int tid  = threadIdx.x;
    const int lane = tid & 31;
    const int warp = tid >> 5;
    const int g  = lane >> 2;
    const int t4 = lane & 3;
    const int wm = (warp >> 1) * 32;
    const int wn = (warp & 1) * 32;

    float acc[2][4][4];
#pragma unroll
    for (int mi = 0; mi < 2; mi++)
#pragma unroll
        for (int ni = 0; ni < 4; ni++)
#pragma unroll
            for (int q = 0; q < 4; q++) acc[mi][ni][q] = 0.f;

    const int lr = tid >> 2;
    const int lc = (tid & 3) * 4;

    for (int k0 = 0; k0 < kE; k0 += 16) {
        __syncthreads();
#pragma unroll
        for (int rr = 0; rr < 2; rr++) {
            const int row = lr + rr * 32;
            float4 va = *(const float4*)(X + ((size_t)row * kS + s) * kE + k0 + lc);
            unsigned* da = &As[row * 20 + lc];
            da[0] = f2tf(va.x); da[1] = f2tf(va.y); da[2] = f2tf(va.z); da[3] = f2tf(va.w);
            float4 vb = *(const float4*)(W + (size_t)(n0 + row) * kE + k0 + lc);
            unsigned* db = &Bs[row * 20 + lc];
            db[0] = f2tf(vb.x); db[1] = f2tf(vb.y); db[2] = f2tf(vb.z); db[3] = f2tf(vb.w);
        }
        __syncthreads();

#pragma unroll
        for (int kk = 0; kk < 2; kk++) {
            const int kb = kk * 8;
            unsigned a[2][4], b[4][2];
#pragma unroll
            for (int mi = 0; mi < 2; mi++) {
                const int ar = wm + mi * 16;
                a[mi][0] = As[(ar + g) * 20 + kb + t4];
                a[mi][1] = As[(ar + g + 8) * 20 + kb + t4];
                a[mi][2] = As[(ar + g) * 20 + kb + t4 + 4];
                a[mi][3] = As[(ar + g + 8) * 20 + kb + t4 + 4];
            }
#pragma unroll
            for (int ni = 0; ni < 4; ni++) {
                const int bc = wn + ni * 8;
                b[ni][0] = Bs[(bc + g) * 20 + kb + t4];
                b[ni][1] = Bs[(bc + g) * 20 + kb + t4 + 4];
            }
#pragma unroll
            for (int mi = 0; mi < 2; mi++)
#pragma unroll
                for (int ni = 0; ni < 4; ni++)
                    mma_tf32(acc[mi][ni], a[mi], b[ni]);
        }
    }

    const size_t rbase = ((size_t)d * kS + s) * kB;
#pragma unroll
    for (int ni = 0; ni < 4; ni++) {
        const int col = n0 + wn + ni * 8 + t4 * 2;
        const float bs0 = bi[col] + bh[col];
        const float bs1 = bi[col + 1] + bh[col + 1];
#pragma unroll
        for (int mi = 0; mi < 2; mi++) {
            const int r0 = wm + mi * 16 + g;
            float2 v;
            v.x = acc[mi][ni][0] + bs0; v.y = acc[mi][ni][1] + bs1;
            *(float2*)&g_gx[(rbase + r0) * kG + col] = v;
            v.x = acc[mi][ni][2] + bs0; v.y = acc[mi][ni][3] + bs1;
            *(float2*)&g_gx[(rbase + r0 + 8) * kG + col] = v;
        }
    }
}

// ---------------------------------------------------------------------------
// Kernel 2: recurrence. 16 clusters of 8 CTAs, 1024 threads/CTA (32 warps).
// CTA rank c owns hidden units [c*32, c*32+32) => 128 gate rows of w_hh,
// 1 row per thread in registers (32 regs: 8 x float4, K interleaved).
// Thread map: r = tid>>3 (row 0..127), ks = tid&7 (K slice of 32).
// Per step: FMA partials -> 3-round reduce-scatter (7 shfls, lane ks ends
// with batch ks) -> publish -> 1 syncthreads -> gates -> shfl-pack float4 ->
// direct DSMEM broadcast to 7 peers -> barrier.cluster (acq/rel orders all).
// Next step's gx prefetched BEFORE the FMA loop (hidden under 4096 FMA cyc).
// ---------------------------------------------------------------------------
constexpr int GP_STRIDE = 132;   // padded: publish stores conflict-free

__global__ void __launch_bounds__(1024, 1) lstm_rec(
    const float* __restrict__ whf, const float* __restrict__ whb,
    const float* __restrict__ h0f, const float* __restrict__ c0f,
    const float* __restrict__ h0b, const float* __restrict__ c0b,
    float* __restrict__ out)
{
    __shared__ float hb[2][8][kH];          // double-buffered h, 8 batches
    __shared__ float gp[8][GP_STRIDE];      // reduced recurrent preacts

    unsigned rank;
    asm("mov.u32 %0, %%cluster_ctarank;" : "=r"(rank));
    unsigned hb_base;
    asm("{ .reg .u64 t; cvta.to.shared.u64 t, %1; cvt.u32.u64 %0, t; }"
        : "=r"(hb_base) : "l"(&hb[0][0][0]));

    const int cid = blockIdx.x >> 3;   // cluster 0..15
    const int dir = cid >> 3;          // 0 fwd, 1 bwd
    const int bg  = cid & 7;
    const int gb0 = bg * 8;
    const int tid = threadIdx.x;

    const float* whh = dir == 0 ? whf : whb;
    const float* h0  = dir == 0 ? h0f : h0b;
    const float* c0  = dir == 0 ? c0f : c0b;

    const int r  = tid >> 3;           // gate row 0..127
    const int ks = tid & 7;            // K slice

    // Local row r -> global w_hh row: gate = r>>5, unit = rank*32 + (r&31)
    const int gr = ((r >> 5) << 8) + (int)rank * 32 + (r & 31);

    // Persistent weight registers: 8 float4 (k = kc*32 + ks*4)
    float4 w[8];
#pragma unroll
    for (int kc = 0; kc < 8; kc++)
        w[kc] = *(const float4*)(whh + (size_t)gr * kH + kc * 32 + ks * 4);

    // Load h0 into buffer 0
    for (int idx = tid; idx < 8 * 64; idx += 1024) {
        const int b = idx >> 6, k4 = (idx & 63) * 4;
        *(float4*)&hb[0][b][k4] = *(const float4*)(h0 + (size_t)(gb0 + b) * kH + k4);
    }

    // Gate-phase mapping (tid < 256): b = tid>>5, u = tid&31
    const int ub = tid >> 5;
    const int uu = tid & 31;
    float cst = 0.f;
    size_t gx_addr0 = 0;
    if (tid < 256) {
        cst = c0[(size_t)(gb0 + ub) * kH + (int)rank * 32 + uu];
        gx_addr0 = ((size_t)dir * kS * kB + (gb0 + ub)) * kG
                   + (size_t)rank * 32 + uu;
    }

    __syncthreads();
    asm volatile("barrier.cluster.arrive.aligned;" ::: "memory");
    asm volatile("barrier.cluster.wait.aligned;" ::: "memory");

    // Preload gx for step 0
    float gx0 = 0.f, gx1 = 0.f, gx2 = 0.f, gx3 = 0.f;
    if (tid < 256) {
        const int t0 = (dir == 0) ? 0 : (kS - 1);
        const size_t a = gx_addr0 + (size_t)t0 * (kB * kG);
        gx0 = g_gx[a]; gx1 = g_gx[a + 256]; gx2 = g_gx[a + 512]; gx3 = g_gx[a + 768];
    }

    int p = 0;
    for (int step = 0; step < kS; step++) {
        const int t = (dir == 0) ? step : (kS - 1 - step);

        // Prefetch NEXT step's gx now; DRAM latency hides under the FMA loop.
        float gn0 = 0.f, gn1 = 0.f, gn2 = 0.f, gn3 = 0.f;
        if (tid < 256 && step + 1 < kS) {
            const int tn = (dir == 0) ? (step + 1) : (kS - 2 - step);
            const size_t a = gx_addr0 + (size_t)tn * (kB * kG);
            gn0 = g_gx[a]; gn1 = g_gx[a + 256]; gn2 = g_gx[a + 512]; gn3 = g_gx[a + 768];
        }

        // Partial dots: 1 row x 8 batches over our 32-element K slice
        float acc[8];
#pragma unroll
        for (int b = 0; b < 8; b++) acc[b] = 0.f;

        const float* hcur = &hb[p][0][0];
#pragma unroll
        for (int kc = 0; kc < 8; kc++) {
            const int k = kc * 32 + ks * 4;
            const float4 wv = w[kc];
#pragma unroll
            for (int b = 0; b < 8; b++) {
                const float4 h4 = *(const float4*)(hcur + b * kH + k);
                acc[b] = fmaf(wv.x, h4.x, fmaf(wv.y, h4.y,
                         fmaf(wv.z, h4.z, fmaf(wv.w, h4.w, acc[b]))));
            }
        }

        // 3-round reduce-scatter over the 8 K-slice lanes: 7 shfls total.
        // After round i, kept batches have low bits equal to ks's low bits.
        float A4[4];
#pragma unroll
        for (int i = 0; i < 4; i++) {
            const float send = (ks & 1) ? acc[2 * i]     : acc[2 * i + 1];
            const float keep = (ks & 1) ? acc[2 * i + 1] : acc[2 * i];
            A4[i] = keep + __shfl_xor_sync(0xffffffffu, send, 1);
        }
        float A2[2];
#pragma unroll
        for (int i = 0; i < 2; i++) {
            const float send = (ks & 2) ? A4[2 * i]     : A4[2 * i + 1];
            const float keep = (ks & 2) ? A4[2 * i + 1] : A4[2 * i];
            A2[i] = keep + __shfl_xor_sync(0xffffffffu, send, 2);
        }
        {
            const float send = (ks & 4) ? A2[0] : A2[1];
            const float keep = (ks & 4) ? A2[1] : A2[0];
            const float dotv = keep + __shfl_xor_sync(0xffffffffu, send, 4);
            gp[ks][r] = dotv;   // full dot for (row r, batch ks)
        }
        __syncthreads();

        if (tid < 256) {
            const float gi = gp[ub][uu]      + gx0;  // i
            const float gf = gp[ub][32 + uu] + gx1;  // f
            const float gg = gp[ub][64 + uu] + gx2;  // g
            const float go = gp[ub][96 + uu] + gx3;  // o
            cst = sigf(gf) * cst + sigf(gi) * tanhf_(gg);
            const float hnew = sigf(go) * tanhf_(cst);

            hb[p ^ 1][ub][(int)rank * 32 + uu] = hnew;
            out[(((size_t)(gb0 + ub)) * kS + t) * 512
                + dir * kH + (int)rank * 32 + uu] = hnew;

            // Pack 4 consecutive h values via shfl, broadcast to 7 peers.
            const float n1 = __shfl_down_sync(0xffffffffu, hnew, 1);
            const float n2 = __shfl_down_sync(0xffffffffu, hnew, 2);
            const float n3 = __shfl_down_sync(0xffffffffu, hnew, 3);
            if ((uu & 3) == 0) {
                const unsigned loff = hb_base +
                    (unsigned)((((p ^ 1) * 8 + ub) * kH)
                               + (int)rank * 32 + uu) * 4u;
#pragma unroll
                for (int pr = 0; pr < 8; pr++) {
                    if (pr == (int)rank) continue;
                    unsigned raddr;
                    asm("mapa.shared::cluster.u32 %0, %1, %2;"
                        : "=r"(raddr) : "r"(loff), "r"(pr));
                    asm volatile("st.shared::cluster.v4.f32 [%0], {%1,%2,%3,%4};"
                                 :: "r"(raddr), "f"(hnew), "f"(n1), "f"(n2), "f"(n3));
                }
            }
        }

        // Release/acquire cluster barrier: orders local hb write + remote
        // DSMEM stores before anyone reads hb[p^1] next step.
        asm volatile("barrier.cluster.arrive.aligned;" ::: "memory");
        asm volatile("barrier.cluster.wait.aligned;" ::: "memory");

        gx0 = gn0; gx1 = gn1; gx2 = gn2; gx3 = gn3;
        p ^= 1;
    }
}

// ---------------------------------------------------------------------------
// Launch
// ---------------------------------------------------------------------------
extern "C" void kernel_launch(void* const* d_in, const int* in_sizes, int n_in,
                              void* d_out, int out_size)
{
    const float* X   = (const float*)d_in[0];
    const float* Wf  = (const float*)d_in[1];
    const float* Whf = (const float*)d_in[2];
    const float* bif = (const float*)d_in[3];
    const float* bhf = (const float*)d_in[4];
    const float* Wb  = (const float*)d_in[5];
    const float* Whb = (const float*)d_in[6];
    const float* bib = (const float*)d_in[7];
    const float* bhb = (const float*)d_in[8];
    const float* h0f = (const float*)d_in[9];
    const float* c0f = (const float*)d_in[10];
    const float* h0b = (const float*)d_in[11];
    const float* c0b = (const float*)d_in[12];
    float* out = (float*)d_out;

    dim3 g1(16, 2048, 2);
    gemm_in<<<g1, 128>>>(X, Wf, bif, bhf, Wb, bib, bhb);

    cudaLaunchConfig_t cfg = {};
    cfg.gridDim = dim3(128, 1, 1);
    cfg.blockDim = dim3(1024, 1, 1);
    cfg.dynamicSmemBytes = 0;
    cfg.stream = 0;
    cudaLaunchAttribute attr[1];
    attr[0].id = cudaLaunchAttributeClusterDimension;
    attr[0].val.clusterDim.x = 8;
    attr[0].val.clusterDim.y = 1;
    attr[0].val.clusterDim.z = 1;
    cfg.attrs = attr;
    cfg.numAttrs = 1;
    cudaLaunchKernelEx(&cfg, lstm_rec, Whf, Whb, h0f, c0f, h0b, c0b, out);
}

// round 9
// speedup vs baseline: 1.7775x; 1.7775x over previous
#include <cuda_runtime.h>

// Problem constants
constexpr int kS = 2048;   // seq len
constexpr int kB = 64;     // batch
constexpr int kE = 512;    // embed
constexpr int kH = 256;    // hidden
constexpr int kG = 1024;   // 4*H

// Scratch for input projections: [2 dirs][S][B][4H] fp32 = 1.07 GB
__device__ float g_gx[2u * 2048u * 64u * 1024u];

// ---------------------------------------------------------------------------
// Helpers
// ---------------------------------------------------------------------------
__device__ __forceinline__ unsigned f2tf(float x) {
    unsigned r;
    asm("cvt.rna.tf32.f32 %0, %1;" : "=r"(r) : "f"(x));
    return r;
}

__device__ __forceinline__ void mma_tf32(float* c, const unsigned* a, const unsigned* b) {
    asm volatile(
        "mma.sync.aligned.m16n8k8.row.col.f32.tf32.tf32.f32 "
        "{%0,%1,%2,%3},{%4,%5,%6,%7},{%8,%9},{%0,%1,%2,%3};"
        : "+f"(c[0]), "+f"(c[1]), "+f"(c[2]), "+f"(c[3])
        : "r"(a[0]), "r"(a[1]), "r"(a[2]), "r"(a[3]), "r"(b[0]), "r"(b[1]));
}

__device__ __forceinline__ float sigf(float x) { return 1.f / (1.f + __expf(-x)); }
__device__ __forceinline__ float tanhf_(float x) { return 1.f - 2.f / (__expf(2.f * x) + 1.f); }

// ---------------------------------------------------------------------------
// Kernel 1: input projection GEMM (tf32 mma.sync), per direction (unchanged)
// ---------------------------------------------------------------------------
__global__ void __launch_bounds__(128) gemm_in(
    const float* __restrict__ X,
    const float* __restrict__ Wf, const float* __restrict__ bif, const float* __restrict__ bhf,
    const float* __restrict__ Wb, const float* __restrict__ bib, const float* __restrict__ bhb)
{
    __shared__ unsigned As[64 * 20];
    __shared__ unsigned Bs[64 * 20];

    const int ntile = blockIdx.x;       // 0..15
    const int s     = blockIdx.y;       // 0..2047
    const int d     = blockIdx.z;       // 0..1
    const float* W  = d == 0 ? Wf : Wb;
    const float* bi = d == 0 ? bif : bib;
    const float* bh = d == 0 ? bhf : bhb;
    const int n0 = ntile * 64;

    const int tid  = threadIdx.x;
    const int lane = tid & 31;
    const int warp = tid >> 5;
    const int g  = lane >> 2;
    const int t4 = lane & 3;
    const int wm = (warp >> 1) * 32;
    const int wn = (warp & 1) * 32;

    float acc[2][4][4];
#pragma unroll
    for (int mi = 0; mi < 2; mi++)
#pragma unroll
        for (int ni = 0; ni < 4; ni++)
#pragma unroll
            for (int q = 0; q < 4; q++) acc[mi][ni][q] = 0.f;

    const int lr = tid >> 2;
    const int lc = (tid & 3) * 4;

    for (int k0 = 0; k0 < kE; k0 += 16) {
        __syncthreads();
#pragma unroll
        for (int rr = 0; rr < 2; rr++) {
            const int row = lr + rr * 32;
            float4 va = *(const float4*)(X + ((size_t)row * kS + s) * kE + k0 + lc);
            unsigned* da = &As[row * 20 + lc];
            da[0] = f2tf(va.x); da[1] = f2tf(va.y); da[2] = f2tf(va.z); da[3] = f2tf(va.w);
            float4 vb = *(const float4*)(W + (size_t)(n0 + row) * kE + k0 + lc);
            unsigned* db = &Bs[row * 20 + lc];
            db[0] = f2tf(vb.x); db[1] = f2tf(vb.y); db[2] = f2tf(vb.z); db[3] = f2tf(vb.w);
        }
        __syncthreads();

#pragma unroll
        for (int kk = 0; kk < 2; kk++) {
            const int kb = kk * 8;
            unsigned a[2][4], b[4][2];
#pragma unroll
            for (int mi = 0; mi < 2; mi++) {
                const int ar = wm + mi * 16;
                a[mi][0] = As[(ar + g) * 20 + kb + t4];
                a[mi][1] = As[(ar + g + 8) * 20 + kb + t4];
                a[mi][2] = As[(ar + g) * 20 + kb + t4 + 4];
                a[mi][3] = As[(ar + g + 8) * 20 + kb + t4 + 4];
            }
#pragma unroll
            for (int ni = 0; ni < 4; ni++) {
                const int bc = wn + ni * 8;
                b[ni][0] = Bs[(bc + g) * 20 + kb + t4];
                b[ni][1] = Bs[(bc + g) * 20 + kb + t4 + 4];
            }
#pragma unroll
            for (int mi = 0; mi < 2; mi++)
#pragma unroll
                for (int ni = 0; ni < 4; ni++)
                    mma_tf32(acc[mi][ni], a[mi], b[ni]);
        }
    }

    const size_t rbase = ((size_t)d * kS + s) * kB;
#pragma unroll
    for (int ni = 0; ni < 4; ni++) {
        const int col = n0 + wn + ni * 8 + t4 * 2;
        const float bs0 = bi[col] + bh[col];
        const float bs1 = bi[col + 1] + bh[col + 1];
#pragma unroll
        for (int mi = 0; mi < 2; mi++) {
            const int r0 = wm + mi * 16 + g;
            float2 v;
            v.x = acc[mi][ni][0] + bs0; v.y = acc[mi][ni][1] + bs1;
            *(float2*)&g_gx[(rbase + r0) * kG + col] = v;
            v.x = acc[mi][ni][2] + bs0; v.y = acc[mi][ni][3] + bs1;
            *(float2*)&g_gx[(rbase + r0 + 8) * kG + col] = v;
        }
    }
}

// ---------------------------------------------------------------------------
// Kernel 2: recurrence on TENSOR CORES. 16 clusters of 8 CTAs, 512 thr/CTA.
// CTA rank c owns hidden units [c*32, c*32+32) => 128 gate rows of w_hh.
// Row ordering inside the CTA: r = unit_local*4 + gate  (gate 0..3 = i,f,g,o)
//   -> global w_hh row = gate*256 + rank*32 + unit_local.
// Warp w (0..15) owns rows [8w, 8w+8) as tf32 A-fragments held PERSISTENTLY
// in 64 regs (a1/a3 lanes = 0: M rows 8..15 of each m16 tile unused).
// Per step: C[16x8]=0; 32 k-steps of (2 LDS h + 1 mma) accumulate K fully
// in-register (NO shfl reduce) -> publish C to gp[batch][row] (conflict-free)
// -> syncthreads -> gate threads read (i,f,g,o) as ONE float4 -> cst/h update
// -> DSMEM broadcast float4 slices to 7 peers -> barrier.cluster.
// ---------------------------------------------------------------------------
constexpr int HB_STR = 260;   // h row stride: bank = (4g + k) % 32, conflict-free
constexpr int GP_STR = 132;   // gp batch stride: conflict-free STS + float4 LDS

__global__ void __launch_bounds__(512, 1) lstm_rec(
    const float* __restrict__ whf, const float* __restrict__ whb,
    const float* __restrict__ h0f, const float* __restrict__ c0f,
    const float* __restrict__ h0b, const float* __restrict__ c0b,
    float* __restrict__ out)
{
    __shared__ float hb[2][8][HB_STR];   // double-buffered h, 8 batches
    __shared__ float gp[8][GP_STR];      // recurrent preacts [batch][row]

    unsigned rank;
    asm("mov.u32 %0, %%cluster_ctarank;" : "=r"(rank));
    unsigned hb_base;
    asm("{ .reg .u64 t; cvta.to.shared.u64 t, %1; cvt.u32.u64 %0, t; }"
        : "=r"(hb_base) : "l"(&hb[0][0][0]));

    const int cid = blockIdx.x >> 3;   // cluster 0..15
    const int dir = cid >> 3;          // 0 fwd, 1 bwd
    const int bg  = cid & 7;
    const int gb0 = bg * 8;
    const int tid = threadIdx.x;
    const int w   = tid >> 5;          // warp 0..15
    const int lane = tid & 31;
    const int g   = lane >> 2;         // fragment group 0..7
    const int t4  = lane & 3;          // thread-in-group

    const float* whh = dir == 0 ? whf : whb;
    const float* h0  = dir == 0 ? h0f : h0b;
    const float* c0  = dir == 0 ? c0f : c0b;

    // Persistent A-fragments: row r = 8w + g; w_hh row = (r&3)*256 + rank*32 + (r>>2)
    const int r    = 8 * w + g;
    const int wrow = (r & 3) * 256 + (int)rank * 32 + (r >> 2);
    unsigned a0[32], a2[32];
#pragma unroll
    for (int kc = 0; kc < 32; kc++) {
        a0[kc] = f2tf(whh[(size_t)wrow * kH + kc * 8 + t4]);
        a2[kc] = f2tf(whh[(size_t)wrow * kH + kc * 8 + t4 + 4]);
    }

    // Load h0 into buffer 0 (tf32-rounded, consistent with mainloop h)
    for (int idx = tid; idx < 8 * 64; idx += 512) {
        const int b = idx >> 6, k4 = (idx & 63) * 4;
        float4 v = *(const float4*)(h0 + (size_t)(gb0 + b) * kH + k4);
        float4 o4;
        o4.x = __uint_as_float(f2tf(v.x)); o4.y = __uint_as_float(f2tf(v.y));
        o4.z = __uint_as_float(f2tf(v.z)); o4.w = __uint_as_float(f2tf(v.w));
        *(float4*)&hb[0][b][k4] = o4;
    }

    // Gate-phase mapping (tid < 256): b = tid>>5, u = tid&31
    const int ub = tid >> 5;
    const int uu = tid & 31;
    float cst = 0.f;
    size_t gx_addr0 = 0;
    if (tid < 256) {
        cst = c0[(size_t)(gb0 + ub) * kH + (int)rank * 32 + uu];
        gx_addr0 = ((size_t)dir * kS * kB + (gb0 + ub)) * kG
                   + (size_t)rank * 32 + uu;
    }

    __syncthreads();
    asm volatile("barrier.cluster.arrive.aligned;" ::: "memory");
    asm volatile("barrier.cluster.wait.aligned;" ::: "memory");

    // Preload gx for step 0
    float gx0 = 0.f, gx1 = 0.f, gx2 = 0.f, gx3 = 0.f;
    if (tid < 256) {
        const int t0 = (dir == 0) ? 0 : (kS - 1);
        const size_t a = gx_addr0 + (size_t)t0 * (kB * kG);
        gx0 = g_gx[a]; gx1 = g_gx[a + 256]; gx2 = g_gx[a + 512]; gx3 = g_gx[a + 768];
    }

    int p = 0;
    for (int step = 0; step < kS; step++) {
        const int t = (dir == 0) ? step : (kS - 1 - step);

        // Prefetch NEXT step's gx (hidden under the mma loop)
        float gn0 = 0.f, gn1 = 0.f, gn2 = 0.f, gn3 = 0.f;
        if (tid < 256 && step + 1 < kS) {
            const int tn = (dir == 0) ? (step + 1) : (kS - 2 - step);
            const size_t a = gx_addr0 + (size_t)tn * (kB * kG);
            gn0 = g_gx[a]; gn1 = g_gx[a + 256]; gn2 = g_gx[a + 512]; gn3 = g_gx[a + 768];
        }

        // Tensor mainloop: C[row r][batch 2t4 / 2t4+1] over full K=256
        float c0a = 0.f, c1a = 0.f, c2a = 0.f, c3a = 0.f;
        const float* hcur = &hb[p][0][0];
        const int hoff = g * HB_STR + t4;
#pragma unroll
        for (int kc = 0; kc < 32; kc++) {
            const unsigned b0 = __float_as_uint(hcur[hoff + kc * 8]);
            const unsigned b1 = __float_as_uint(hcur[hoff + kc * 8 + 4]);
            asm volatile(
                "mma.sync.aligned.m16n8k8.row.col.f32.tf32.tf32.f32 "
                "{%0,%1,%2,%3},{%4,%5,%6,%7},{%8,%9},{%0,%1,%2,%3};"
                : "+f"(c0a), "+f"(c1a), "+f"(c2a), "+f"(c3a)
                : "r"(a0[kc]), "r"(0u), "r"(a2[kc]), "r"(0u), "r"(b0), "r"(b1));
        }

        // Publish: gp[batch][row] (bank = (8t4 + 8w + g) % 32 -> conflict-free)
        gp[2 * t4][r]     = c0a;
        gp[2 * t4 + 1][r] = c1a;
        __syncthreads();

        if (tid < 256) {
            // rows 4uu..4uu+3 = gates (i,f,g,o) of unit uu -> one float4
            const float4 ga = *(const float4*)&gp[ub][4 * uu];
            const float gi = ga.x + gx0;
            const float gf = ga.y + gx1;
            const float gg = ga.z + gx2;
            const float go = ga.w + gx3;
            cst = sigf(gf) * cst + sigf(gi) * tanhf_(gg);
            const float hnew = sigf(go) * tanhf_(cst);
            const float hr = __uint_as_float(f2tf(hnew));  // rounded for recurrence

            hb[p ^ 1][ub][(int)rank * 32 + uu] = hr;

            // Pack 4 consecutive h values, broadcast to the 7 peer CTAs
            const float n1 = __shfl_down_sync(0xffffffffu, hr, 1);
            const float n2 = __shfl_down_sync(0xffffffffu, hr, 2);
            const float n3 = __shfl_down_sync(0xffffffffu, hr, 3);
            if ((uu & 3) == 0) {
                const unsigned loff = hb_base +
                    (unsigned)((((p ^ 1) * 8 + ub) * HB_STR)
                               + (int)rank * 32 + uu) * 4u;
#pragma unroll
                for (int pr = 0; pr < 8; pr++) {
                    if (pr == (int)rank) continue;
                    unsigned raddr;
                    asm("mapa.shared::cluster.u32 %0, %1, %2;"
                        : "=r"(raddr) : "r"(loff), "r"(pr));
                    asm volatile("st.shared::cluster.v4.f32 [%0], {%1,%2,%3,%4};"
                                 :: "r"(raddr), "f"(hr), "f"(n1), "f"(n2), "f"(n3));
                }
            }

            out[(((size_t)(gb0 + ub)) * kS + t) * 512
                + dir * kH + (int)rank * 32 + uu] = hnew;
        }

        asm volatile("barrier.cluster.arrive.aligned;" ::: "memory");
        asm volatile("barrier.cluster.wait.aligned;" ::: "memory");

        gx0 = gn0; gx1 = gn1; gx2 = gn2; gx3 = gn3;
        p ^= 1;
    }
}

// ---------------------------------------------------------------------------
// Launch
// ---------------------------------------------------------------------------
extern "C" void kernel_launch(void* const* d_in, const int* in_sizes, int n_in,
                              void* d_out, int out_size)
{
    const float* X   = (const float*)d_in[0];
    const float* Wf  = (const float*)d_in[1];
    const float* Whf = (const float*)d_in[2];
    const float* bif = (const float*)d_in[3];
    const float* bhf = (const float*)d_in[4];
    const float* Wb  = (const float*)d_in[5];
    const float* Whb = (const float*)d_in[6];
    const float* bib = (const float*)d_in[7];
    const float* bhb = (const float*)d_in[8];
    const float* h0f = (const float*)d_in[9];
    const float* c0f = (const float*)d_in[10];
    const float* h0b = (const float*)d_in[11];
    const float* c0b = (const float*)d_in[12];
    float* out = (float*)d_out;

    dim3 g1(16, 2048, 2);
    gemm_in<<<g1, 128>>>(X, Wf, bif, bhf, Wb, bib, bhb);

    cudaLaunchConfig_t cfg = {};
    cfg.gridDim = dim3(128, 1, 1);
    cfg.blockDim = dim3(512, 1, 1);
    cfg.dynamicSmemBytes = 0;
    cfg.stream = 0;
    cudaLaunchAttribute attr[1];
    attr[0].id = cudaLaunchAttributeClusterDimension;
    attr[0].val.clusterDim.x = 8;
    attr[0].val.clusterDim.y = 1;
    attr[0].val.clusterDim.z = 1;
    cfg.attrs = attr;
    cfg.numAttrs = 1;
    cudaLaunchKernelEx(&cfg, lstm_rec, Whf, Whb, h0f, c0f, h0b, c0b, out);
}

// round 10
// speedup vs baseline: 2.4215x; 1.3623x over previous
#include <cuda_runtime.h>

// Problem constants
constexpr int kS = 2048;   // seq len
constexpr int kB = 64;     // batch
constexpr int kE = 512;    // embed
constexpr int kH = 256;    // hidden
constexpr int kG = 1024;   // 4*H

// Scratch for input projections: [2 dirs][S][B][4H] fp32 = 1.07 GB
__device__ float g_gx[2u * 2048u * 64u * 1024u];

// ---------------------------------------------------------------------------
// Helpers
// ---------------------------------------------------------------------------
__device__ __forceinline__ unsigned f2tf(float x) {
    unsigned r;
    asm("cvt.rna.tf32.f32 %0, %1;" : "=r"(r) : "f"(x));
    return r;
}

__device__ __forceinline__ void mma_tf32(float* c, const unsigned* a, const unsigned* b) {
    asm volatile(
        "mma.sync.aligned.m16n8k8.row.col.f32.tf32.tf32.f32 "
        "{%0,%1,%2,%3},{%4,%5,%6,%7},{%8,%9},{%0,%1,%2,%3};"
        : "+f"(c[0]), "+f"(c[1]), "+f"(c[2]), "+f"(c[3])
        : "r"(a[0]), "r"(a[1]), "r"(a[2]), "r"(a[3]), "r"(b[0]), "r"(b[1]));
}

__device__ __forceinline__ float sigf(float x) { return 1.f / (1.f + __expf(-x)); }
__device__ __forceinline__ float tanhf_(float x) { return 1.f - 2.f / (__expf(2.f * x) + 1.f); }

// ---------------------------------------------------------------------------
// Kernel 1: input projection GEMM (tf32 mma.sync), per direction (unchanged)
// ---------------------------------------------------------------------------
__global__ void __launch_bounds__(128) gemm_in(
    const float* __restrict__ X,
    const float* __restrict__ Wf, const float* __restrict__ bif, const float* __restrict__ bhf,
    const float* __restrict__ Wb, const float* __restrict__ bib, const float* __restrict__ bhb)
{
    __shared__ unsigned As[64 * 20];
    __shared__ unsigned Bs[64 * 20];

    const int ntile = blockIdx.x;       // 0..15
    const int s     = blockIdx.y;       // 0..2047
    const int d     = blockIdx.z;       // 0..1
    const float* W  = d == 0 ? Wf : Wb;
    const float* bi = d == 0 ? bif : bib;
    const float* bh = d == 0 ? bhf : bhb;
    const int n0 = ntile * 64;

    const int tid  = threadIdx.x;
    const int lane = tid & 31;
    const int warp = tid >> 5;
    const int g  = lane >> 2;
    const int t4 = lane & 3;
    const int wm = (warp >> 1) * 32;
    const int wn = (warp & 1) * 32;

    float acc[2][4][4];
#pragma unroll
    for (int mi = 0; mi < 2; mi++)
#pragma unroll
        for (int ni = 0; ni < 4; ni++)
#pragma unroll
            for (int q = 0; q < 4; q++) acc[mi][ni][q] = 0.f;

    const int lr = tid >> 2;
    const int lc = (tid & 3) * 4;

    for (int k0 = 0; k0 < kE; k0 += 16) {
        __syncthreads();
#pragma unroll
        for (int rr = 0; rr < 2; rr++) {
            const int row = lr + rr * 32;
            float4 va = *(const float4*)(X + ((size_t)row * kS + s) * kE + k0 + lc);
            unsigned* da = &As[row * 20 + lc];
            da[0] = f2tf(va.x); da[1] = f2tf(va.y); da[2] = f2tf(va.z); da[3] = f2tf(va.w);
            float4 vb = *(const float4*)(W + (size_t)(n0 + row) * kE + k0 + lc);
            unsigned* db = &Bs[row * 20 + lc];
            db[0] = f2tf(vb.x); db[1] = f2tf(vb.y); db[2] = f2tf(vb.z); db[3] = f2tf(vb.w);
        }
        __syncthreads();

#pragma unroll
        for (int kk = 0; kk < 2; kk++) {
            const int kb = kk * 8;
            unsigned a[2][4], b[4][2];
#pragma unroll
            for (int mi = 0; mi < 2; mi++) {
                const int ar = wm + mi * 16;
                a[mi][0] = As[(ar + g) * 20 + kb + t4];
                a[mi][1] = As[(ar + g + 8) * 20 + kb + t4];
                a[mi][2] = As[(ar + g) * 20 + kb + t4 + 4];
                a[mi][3] = As[(ar + g + 8) * 20 + kb + t4 + 4];
            }
#pragma unroll
            for (int ni = 0; ni < 4; ni++) {
                const int bc = wn + ni * 8;
                b[ni][0] = Bs[(bc + g) * 20 + kb + t4];
                b[ni][1] = Bs[(bc + g) * 20 + kb + t4 + 4];
            }
#pragma unroll
            for (int mi = 0; mi < 2; mi++)
#pragma unroll
                for (int ni = 0; ni < 4; ni++)
                    mma_tf32(acc[mi][ni], a[mi], b[ni]);
        }
    }

    const size_t rbase = ((size_t)d * kS + s) * kB;
#pragma unroll
    for (int ni = 0; ni < 4; ni++) {
        const int col = n0 + wn + ni * 8 + t4 * 2;
        const float bs0 = bi[col] + bh[col];
        const float bs1 = bi[col + 1] + bh[col + 1];
#pragma unroll
        for (int mi = 0; mi < 2; mi++) {
            const int r0 = wm + mi * 16 + g;
            float2 v;
            v.x = acc[mi][ni][0] + bs0; v.y = acc[mi][ni][1] + bs1;
            *(float2*)&g_gx[(rbase + r0) * kG + col] = v;
            v.x = acc[mi][ni][2] + bs0; v.y = acc[mi][ni][3] + bs1;
            *(float2*)&g_gx[(rbase + r0 + 8) * kG + col] = v;
        }
    }
}

// ---------------------------------------------------------------------------
// Kernel 2: recurrence on tensor cores. 16 clusters of 8 CTAs, 256 thr/CTA.
// CTA rank c owns hidden units [c*32, c*32+32) => 128 gate rows of w_hh.
// Row ordering: r = unit_local*4 + gate -> w_hh row (r&3)*256 + rank*32+(r>>2).
// 8 warps, each owns 16 rows (r = 16w+g and 16w+g+8) as FULL m16n8k8 tf32
// A-fragments, persistent in 128 regs. Per step: 32 mma accumulating K=256
// in-register over TWO independent chains (even/odd kc) -> publish C ->
// sync -> gates (float4 read) -> DSMEM float4 broadcast to 7 peers ->
// mbarrier handshake (2 phase-alternating mbars, count=8, release-arrive by
// 8 threads after fence.acq_rel.cluster; acquire try_wait by all). No
// per-step barrier.cluster => no CCTL.IVALL L1 flush, cheaper sync.
// ---------------------------------------------------------------------------
constexpr int HB_STR = 260;   // h row stride: conflict-free b-frag LDS
constexpr int GP_STR = 132;   // gp batch stride: conflict-free STS + float4 LDS

__global__ void __launch_bounds__(256, 1) lstm_rec(
    const float* __restrict__ whf, const float* __restrict__ whb,
    const float* __restrict__ h0f, const float* __restrict__ c0f,
    const float* __restrict__ h0b, const float* __restrict__ c0b,
    float* __restrict__ out)
{
    __shared__ float hb[2][8][HB_STR];          // double-buffered h, 8 batches
    __shared__ float gp[8][GP_STR];             // recurrent preacts [batch][row]
    __shared__ alignas(8) unsigned long long mbar[2];

    unsigned rank;
    asm("mov.u32 %0, %%cluster_ctarank;" : "=r"(rank));
    unsigned hb_base;
    asm("{ .reg .u64 t; cvta.to.shared.u64 t, %1; cvt.u32.u64 %0, t; }"
        : "=r"(hb_base) : "l"(&hb[0][0][0]));
    unsigned mb_base;
    asm("{ .reg .u64 t; cvta.to.shared.u64 t, %1; cvt.u32.u64 %0, t; }"
        : "=r"(mb_base) : "l"(&mbar[0]));

    const int cid = blockIdx.x >> 3;   // cluster 0..15
    const int dir = cid >> 3;          // 0 fwd, 1 bwd
    const int bg  = cid & 7;
    const int gb0 = bg * 8;
    const int tid = threadIdx.x;
    const int w    = tid >> 5;         // warp 0..7
    const int lane = tid & 31;
    const int g    = lane >> 2;        // fragment group 0..7
    const int t4   = lane & 3;         // thread-in-group

    const float* whh = dir == 0 ? whf : whb;
    const float* h0  = dir == 0 ? h0f : h0b;
    const float* c0  = dir == 0 ? c0f : c0b;

    // Init mbarriers (count = 8 arrivals: one per cluster CTA)
    if (tid == 0) {
        asm volatile("mbarrier.init.shared.b64 [%0], %1;" :: "r"(mb_base), "r"(8u) : "memory");
        asm volatile("mbarrier.init.shared.b64 [%0], %1;" :: "r"(mb_base + 8), "r"(8u) : "memory");
    }

    // Persistent FULL-M A-fragments: rows r_lo = 16w+g, r_hi = r_lo+8
    const int r_lo = 16 * w + g;
    const int r_hi = r_lo + 8;
    const int wr_lo = (r_lo & 3) * 256 + (int)rank * 32 + (r_lo >> 2);
    const int wr_hi = (r_hi & 3) * 256 + (int)rank * 32 + (r_hi >> 2);
    unsigned a0[32], a1[32], a2[32], a3[32];
#pragma unroll
    for (int kc = 0; kc < 32; kc++) {
        a0[kc] = f2tf(whh[(size_t)wr_lo * kH + kc * 8 + t4]);
        a1[kc] = f2tf(whh[(size_t)wr_hi * kH + kc * 8 + t4]);
        a2[kc] = f2tf(whh[(size_t)wr_lo * kH + kc * 8 + t4 + 4]);
        a3[kc] = f2tf(whh[(size_t)wr_hi * kH + kc * 8 + t4 + 4]);
    }

    // Load h0 into buffer 0 (tf32-rounded, consistent with mainloop h)
    for (int idx = tid; idx < 8 * 64; idx += 256) {
        const int b = idx >> 6, k4 = (idx & 63) * 4;
        float4 v = *(const float4*)(h0 + (size_t)(gb0 + b) * kH + k4);
        float4 o4;
        o4.x = __uint_as_float(f2tf(v.x)); o4.y = __uint_as_float(f2tf(v.y));
        o4.z = __uint_as_float(f2tf(v.z)); o4.w = __uint_as_float(f2tf(v.w));
        *(float4*)&hb[0][b][k4] = o4;
    }

    // Gate-phase mapping: all 256 threads, b = tid>>5 (== w), u = tid&31
    const int ub = w;
    const int uu = lane;
    float cst = c0[(size_t)(gb0 + ub) * kH + (int)rank * 32 + uu];
    const size_t gx_addr0 = ((size_t)dir * kS * kB + (gb0 + ub)) * kG
                            + (size_t)rank * 32 + uu;

    __syncthreads();
    // One-time cluster barrier: peers' mbarrier init + h0 visible before use
    asm volatile("barrier.cluster.arrive.aligned;" ::: "memory");
    asm volatile("barrier.cluster.wait.aligned;" ::: "memory");

    // Preload gx for step 0
    float gx0, gx1, gx2, gx3;
    {
        const int t0 = (dir == 0) ? 0 : (kS - 1);
        const size_t a = gx_addr0 + (size_t)t0 * (kB * kG);
        gx0 = g_gx[a]; gx1 = g_gx[a + 256]; gx2 = g_gx[a + 512]; gx3 = g_gx[a + 768];
    }

    int p = 0;
    for (int step = 0; step < kS; step++) {
        const int t = (dir == 0) ? step : (kS - 1 - step);

        // Prefetch NEXT step's gx (hidden under the mma loop)
        float gn0 = 0.f, gn1 = 0.f, gn2 = 0.f, gn3 = 0.f;
        if (step + 1 < kS) {
            const int tn = (dir == 0) ? (step + 1) : (kS - 2 - step);
            const size_t a = gx_addr0 + (size_t)tn * (kB * kG);
            gn0 = g_gx[a]; gn1 = g_gx[a + 256]; gn2 = g_gx[a + 512]; gn3 = g_gx[a + 768];
        }

        // Tensor mainloop over K=256: two independent accumulation chains
        float cE[4] = {0.f, 0.f, 0.f, 0.f};
        float cO[4] = {0.f, 0.f, 0.f, 0.f};
        const float* hcur = &hb[p][0][0];
        const int hoff = g * HB_STR + t4;
#pragma unroll
        for (int kc = 0; kc < 32; kc += 2) {
            {
                const unsigned b0 = __float_as_uint(hcur[hoff + kc * 8]);
                const unsigned b1 = __float_as_uint(hcur[hoff + kc * 8 + 4]);
                const unsigned af[4] = {a0[kc], a1[kc], a2[kc], a3[kc]};
                const unsigned bf[2] = {b0, b1};
                mma_tf32(cE, af, bf);
            }
            {
                const unsigned b0 = __float_as_uint(hcur[hoff + (kc + 1) * 8]);
                const unsigned b1 = __float_as_uint(hcur[hoff + (kc + 1) * 8 + 4]);
                const unsigned af[4] = {a0[kc + 1], a1[kc + 1], a2[kc + 1], a3[kc + 1]};
                const unsigned bf[2] = {b0, b1};
                mma_tf32(cO, af, bf);
            }
        }

        // Publish C: gp[batch][row]; banks (8t4 + r) % 32 -> conflict-free
        gp[2 * t4][r_lo]     = cE[0] + cO[0];
        gp[2 * t4 + 1][r_lo] = cE[1] + cO[1];
        gp[2 * t4][r_hi]     = cE[2] + cO[2];
        gp[2 * t4 + 1][r_hi] = cE[3] + cO[3];
        __syncthreads();

        // Gates: rows 4uu..4uu+3 = (i,f,g,o) of unit uu -> one float4
        const float4 ga = *(const float4*)&gp[ub][4 * uu];
        const float gi = ga.x + gx0;
        const float gf = ga.y + gx1;
        const float gg = ga.z + gx2;
        const float go = ga.w + gx3;
        cst = sigf(gf) * cst + sigf(gi) * tanhf_(gg);
        const float hnew = sigf(go) * tanhf_(cst);
        const float hr = __uint_as_float(f2tf(hnew));   // rounded for recurrence

        hb[p ^ 1][ub][(int)rank * 32 + uu] = hr;
        out[(((size_t)(gb0 + ub)) * kS + t) * 512
            + dir * kH + (int)rank * 32 + uu] = hnew;

        if (step + 1 < kS) {
            // Pack 4 consecutive h values, broadcast to the 7 peer CTAs
            const float n1 = __shfl_down_sync(0xffffffffu, hr, 1);
            const float n2 = __shfl_down_sync(0xffffffffu, hr, 2);
            const float n3 = __shfl_down_sync(0xffffffffu, hr, 3);
            if ((uu & 3) == 0) {
                const unsigned loff = hb_base +
                    (unsigned)((((p ^ 1) * 8 + ub) * HB_STR)
                               + (int)rank * 32 + uu) * 4u;
#pragma unroll
                for (int pr = 0; pr < 8; pr++) {
                    if (pr == (int)rank) continue;
                    unsigned raddr;
                    asm("mapa.shared::cluster.u32 %0, %1, %2;"
                        : "=r"(raddr) : "r"(loff), "r"(pr));
                    asm volatile("st.shared::cluster.v4.f32 [%0], {%1,%2,%3,%4};"
                                 :: "r"(raddr), "f"(hr), "f"(n1), "f"(n2), "f"(n3));
                }
            }

            // All local reads of hb[p] and writes of hb[p^1] done -> handshake
            __syncthreads();
            const unsigned mb_q = mb_base + (unsigned)(((step + 1) & 1) * 8);
            if (tid < 8) {
                asm volatile("fence.acq_rel.cluster;" ::: "memory");
                unsigned raddr;
                asm("mapa.shared::cluster.u32 %0, %1, %2;"
                    : "=r"(raddr) : "r"(mb_q), "r"(tid));
                asm volatile("mbarrier.arrive.release.cluster.shared::cluster.b64 _, [%0];"
                             :: "r"(raddr) : "memory");
            }
            // Wait: all 8 CTAs arrived => h(t) complete everywhere AND every
            // CTA finished reading hb[p] (safe to overwrite next step).
            const unsigned par = (unsigned)((step >> 1) & 1);
            unsigned done = 0;
            while (!done) {
                asm volatile(
                    "{\n\t.reg .pred p;\n\t"
                    "mbarrier.try_wait.parity.acquire.cluster.shared::cta.b64 p, [%1], %2;\n\t"
                    "selp.b32 %0, 1, 0, p;\n\t}"
                    : "=r"(done) : "r"(mb_q), "r"(par) : "memory");
            }
        }

        gx0 = gn0; gx1 = gn1; gx2 = gn2; gx3 = gn3;
        p ^= 1;
    }

    // Keep SMEM alive until all peers are past their last remote stores
    asm volatile("barrier.cluster.arrive.aligned;" ::: "memory");
    asm volatile("barrier.cluster.wait.aligned;" ::: "memory");
}

// ---------------------------------------------------------------------------
// Launch
// ---------------------------------------------------------------------------
extern "C" void kernel_launch(void* const* d_in, const int* in_sizes, int n_in,
                              void* d_out, int out_size)
{
    const float* X   = (const float*)d_in[0];
    const float* Wf  = (const float*)d_in[1];
    const float* Whf = (const float*)d_in[2];
    const float* bif = (const float*)d_in[3];
    const float* bhf = (const float*)d_in[4];
    const float* Wb  = (const float*)d_in[5];
    const float* Whb = (const float*)d_in[6];
    const float* bib = (const float*)d_in[7];
    const float* bhb = (const float*)d_in[8];
    const float* h0f = (const float*)d_in[9];
    const float* c0f = (const float*)d_in[10];
    const float* h0b = (const float*)d_in[11];
    const float* c0b = (const float*)d_in[12];
    float* out = (float*)d_out;

    dim3 g1(16, 2048, 2);
    gemm_in<<<g1, 128>>>(X, Wf, bif, bhf, Wb, bib, bhb);

    cudaLaunchConfig_t cfg = {};
    cfg.gridDim = dim3(128, 1, 1);
    cfg.blockDim = dim3(256, 1, 1);
    cfg.dynamicSmemBytes = 0;
    cfg.stream = 0;
    cudaLaunchAttribute attr[1];
    attr[0].id = cudaLaunchAttributeClusterDimension;
    attr[0].val.clusterDim.x = 8;
    attr[0].val.clusterDim.y = 1;
    attr[0].val.clusterDim.z = 1;
    cfg.attrs = attr;
    cfg.numAttrs = 1;
    cudaLaunchKernelEx(&cfg, lstm_rec, Whf, Whb, h0f, c0f, h0b, c0b, out);
}